// round 7
// baseline (speedup 1.0000x reference)
#include <cuda_runtime.h>
#include <cuda_bf16.h>

#define D 4096
#define THREADS 256

// Bank swizzle: phys = i ^ g(i), g = (i>>4) & 0x1C   (i6->b2, i7->b3, i8->b4)
// Conflict-free (rank-5 injective bank maps) for all shared patterns used here
// (verified R6). g never touches bits [1:0] => float4 groups stay aligned.
__device__ __forceinline__ int swz(int i) {
    return i ^ ((i >> 4) & 0x1C);
}

// Packed butterfly via f32x2: 2 butterflies in 2 instructions.
__device__ __forceinline__ void bfly2(float& a0, float& a1, float& b0, float& b1) {
    asm("{\n\t"
        ".reg .b32 m;\n\t"
        ".reg .b64 ra, rb, rs, rd, rn;\n\t"
        "mov.b32 m, 0xBF800000;\n\t"
        "mov.b64 rn, {m, m};\n\t"
        "mov.b64 ra, {%0, %1};\n\t"
        "mov.b64 rb, {%2, %3};\n\t"
        "add.rn.f32x2 rs, ra, rb;\n\t"
        "fma.rn.f32x2 rd, rb, rn, ra;\n\t"
        "mov.b64 {%0, %1}, rs;\n\t"
        "mov.b64 {%2, %3}, rd;\n\t"
        "}" : "+f"(a0), "+f"(a1), "+f"(b0), "+f"(b1));
}

// Packed scale: (a0,a1) *= (c,c)
__device__ __forceinline__ void scale2(float& a0, float& a1, float c) {
    asm("{\n\t"
        ".reg .b64 ra, rs, rm;\n\t"
        "mov.b64 ra, {%0, %1};\n\t"
        "mov.b64 rs, {%2, %2};\n\t"
        "mul.rn.f32x2 rm, ra, rs;\n\t"
        "mov.b64 {%0, %1}, rm;\n\t"
        "}" : "+f"(a0), "+f"(a1) : "f"(c));
}

// 16-point FWHT: reg bits 1..3 packed (pairs along bit 0), bit 0 scalar.
__device__ __forceinline__ void fwht16p(float r[16]) {
#pragma unroll
    for (int hp = 1; hp < 8; hp <<= 1) {
#pragma unroll
        for (int m = 0; m < 8; m++) {
            if (!(m & hp)) {
                bfly2(r[2 * m], r[2 * m + 1],
                      r[2 * (m | hp)], r[2 * (m | hp) + 1]);
            }
        }
    }
#pragma unroll
    for (int m = 0; m < 8; m++) {
        float a = r[2 * m], b = r[2 * m + 1];
        r[2 * m]     = a + b;
        r[2 * m + 1] = a - b;
    }
}

__global__ __launch_bounds__(THREADS, 5)
void rht_kernel(const float* __restrict__ x,
                const float* __restrict__ signs,
                float* __restrict__ out,
                int n_rows, int stride) {
    __shared__ float s[2][D];

    const int t = threadIdx.x;

    const int f4w   = t ^ ((t >> 4) & 7);             // pass-1 STS.128 index
    const int base2 = ((t >> 2) << 6) | (t & 3);
    const int sb2   = swz(base2);
    const int base3 = ((t >> 6) << 10) | (t & 63);    // bits 6..9 zero -> swz=id

    // signs are exactly +/-1: pack this thread's 16 sign bits into one word.
    // bit (h*4+j) = signbit of signs[(h<<10)|(t<<2)|j]
    unsigned smask = 0;
#pragma unroll
    for (int h = 0; h < 4; h++) {
#pragma unroll
        for (int j = 0; j < 4; j++) {
            smask |= (__float_as_uint(signs[(h << 10) | (t << 2) | j]) >> 31)
                     << (h * 4 + j);
        }
    }

    // prefetch first row (streaming: no reuse, keep L2 clean)
    int row = blockIdx.x;
    float4 xa[4];
    {
        const float4* __restrict__ xv4 =
            reinterpret_cast<const float4*>(x + (size_t)row * D);
#pragma unroll
        for (int h = 0; h < 4; h++) xa[h] = __ldcs(xv4 + (h << 8) + t);
    }

    int buf = 0;
    while (row < n_rows) {
        float r[16];

        // ---- Pass A: bits {0,1,10,11}; sign applied as XOR on sign bit ----
#pragma unroll
        for (int h = 0; h < 4; h++) {
            const float v[4] = { xa[h].x, xa[h].y, xa[h].z, xa[h].w };
#pragma unroll
            for (int j = 0; j < 4; j++) {
                const int b = h * 4 + j;
                r[b] = __uint_as_float(__float_as_uint(v[j]) ^
                                       ((smask << (31 - b)) & 0x80000000u));
            }
        }
        fwht16p(r);

        // ---- remap 1: 4x STS.128 at i = (h<<10)|(t<<2)|j ----
        {
            float4* __restrict__ s4 = reinterpret_cast<float4*>(s[buf]);
#pragma unroll
            for (int h = 0; h < 4; h++) {
                s4[(h << 8) + f4w] =
                    make_float4(r[h * 4 + 0], r[h * 4 + 1],
                                r[h * 4 + 2], r[h * 4 + 3]);
            }
        }

        // ---- prefetch next row (overlaps barrier + passes B/C) ----
        const int nrow = row + stride;
        {
            const int prow = (nrow < n_rows) ? nrow : row;  // safe clamp
            const float4* __restrict__ xv4 =
                reinterpret_cast<const float4*>(x + (size_t)prow * D);
#pragma unroll
            for (int h = 0; h < 4; h++) xa[h] = __ldcs(xv4 + (h << 8) + t);
        }

        __syncthreads();

        // ---- Pass B: bits {2,3,4,5} ----
#pragma unroll
        for (int k = 0; k < 16; k++) {
            r[k] = s[buf][sb2 ^ (k << 2)];
        }
        fwht16p(r);
#pragma unroll
        for (int k = 0; k < 16; k++) {
            s[buf][sb2 ^ (k << 2)] = r[k];
        }
        __syncthreads();

        // ---- Pass C: bits {6,7,8,9} ----
#pragma unroll
        for (int k = 0; k < 16; k++) {
            r[k] = s[buf][base3 ^ (k << 6) ^ ((k & 7) << 2)];
        }
        fwht16p(r);

        // normalize by D^-1/2 = 1/64 (exact) using packed muls
#pragma unroll
        for (int m = 0; m < 8; m++) scale2(r[2 * m], r[2 * m + 1], 0.015625f);

        // ---- streaming coalesced stores at i = base3 + k*64 ----
        float* __restrict__ orow = out + (size_t)row * D;
#pragma unroll
        for (int k = 0; k < 16; k++) {
            __stcs(&orow[base3 + (k << 6)], r[k]);
        }

        row = nrow;
        buf ^= 1;
    }
}

extern "C" void kernel_launch(void* const* d_in, const int* in_sizes, int n_in,
                              void* d_out, int out_size) {
    const float* x     = (const float*)d_in[0];
    const float* signs = (const float*)d_in[1];
    float* out = (float*)d_out;

    const int n_rows = in_sizes[0] / D;  // 8192

    int sm_count = 152;                   // GB300 default
    cudaDeviceGetAttribute(&sm_count, cudaDevAttrMultiProcessorCount, 0);
    int grid = sm_count * 5;              // one persistent wave at occ 5
    if (grid > n_rows) grid = n_rows;

    rht_kernel<<<grid, THREADS>>>(x, signs, out, n_rows, grid);
}